// round 1
// baseline (speedup 1.0000x reference)
#include <cuda_runtime.h>
#include <math.h>

#define BATCH 4
#define CH    512
#define HWN   4096
#define NGROUPS 32
#define CPG   16   // channels per group

// ---------------- scratch (device globals; allocation-free) ----------------
__device__ float g_h[(size_t)BATCH * CH * HWN];            // 32 MB
__device__ float g_q[(size_t)BATCH * CH * HWN];            // 32 MB
__device__ float g_k[(size_t)BATCH * CH * HWN];            // 32 MB
__device__ float g_v[(size_t)BATCH * CH * HWN];            // 32 MB
__device__ float g_o[(size_t)BATCH * CH * HWN];            // 32 MB
__device__ float g_s[(size_t)BATCH * HWN * HWN];           // 256 MB attention matrix

// ---------------- GroupNorm ----------------
// one block per (batch, group); reduce over CPG*HWN = 65536 elems
__global__ void gn_kernel(const float* __restrict__ x,
                          const float* __restrict__ gamma,
                          const float* __restrict__ beta,
                          float* __restrict__ h) {
    const int b = blockIdx.x / NGROUPS;
    const int g = blockIdx.x % NGROUPS;
    const int n = CPG * HWN;
    const float* xp = x + ((size_t)b * CH + (size_t)g * CPG) * HWN;
    float*       hp = h + ((size_t)b * CH + (size_t)g * CPG) * HWN;

    float s = 0.f, ss = 0.f;
    for (int i = threadIdx.x; i < n; i += 256) {
        float v = xp[i];
        s += v; ss += v * v;
    }
    __shared__ float sh1[256], sh2[256];
    sh1[threadIdx.x] = s; sh2[threadIdx.x] = ss;
    __syncthreads();
    for (int o = 128; o > 0; o >>= 1) {
        if (threadIdx.x < o) {
            sh1[threadIdx.x] += sh1[threadIdx.x + o];
            sh2[threadIdx.x] += sh2[threadIdx.x + o];
        }
        __syncthreads();
    }
    const float mean = sh1[0] / (float)n;
    const float var  = sh2[0] / (float)n - mean * mean;
    const float inv  = rsqrtf(var + 1e-6f);

    for (int i = threadIdx.x; i < n; i += 256) {
        int c = g * CPG + i / HWN;
        hp[i] = (xp[i] - mean) * inv * gamma[c] + beta[c];
    }
}

// ---------------- Projection GEMM ----------------
// Y[b,m,n] = sum_k W[m,k] * Hin[b,k,n] + bias[m] (+ residual)
// M = CH rows, N = HWN cols, K = CH
template <bool RES>
__global__ void proj_kernel(const float* __restrict__ W,
                            const float* __restrict__ bias,
                            const float* __restrict__ Hin,
                            const float* __restrict__ res,
                            float* __restrict__ Y) {
    const int BM = 64, BN = 64, BK = 16;
    const int b  = blockIdx.z;
    const int m0 = blockIdx.y * BM;
    const int n0 = blockIdx.x * BN;
    const float* Hb = Hin + (size_t)b * CH * HWN;

    __shared__ __align__(16) float As[BK][BM];
    __shared__ __align__(16) float Bs[BK][BN];

    const int tid = threadIdx.x;
    const int rm = (tid / 16) * 4;
    const int rn = (tid % 16) * 4;
    float acc[4][4] = {};

    for (int k0 = 0; k0 < CH; k0 += BK) {
        #pragma unroll
        for (int i = 0; i < 4; i++) {
            int e = tid + i * 256;
            int m = e / BK, k = e % BK;
            As[k][m] = W[(size_t)(m0 + m) * CH + k0 + k];
        }
        #pragma unroll
        for (int i = 0; i < 4; i++) {
            int e = tid + i * 256;
            int k = e / BN, nn = e % BN;
            Bs[k][nn] = Hb[(size_t)(k0 + k) * HWN + n0 + nn];
        }
        __syncthreads();
        #pragma unroll
        for (int k = 0; k < BK; k++) {
            float4 a4 = *reinterpret_cast<const float4*>(&As[k][rm]);
            float4 b4 = *reinterpret_cast<const float4*>(&Bs[k][rn]);
            float a[4] = {a4.x, a4.y, a4.z, a4.w};
            float bb[4] = {b4.x, b4.y, b4.z, b4.w};
            #pragma unroll
            for (int i = 0; i < 4; i++)
                #pragma unroll
                for (int j = 0; j < 4; j++)
                    acc[i][j] += a[i] * bb[j];
        }
        __syncthreads();
    }

    #pragma unroll
    for (int i = 0; i < 4; i++) {
        const float bi = bias[m0 + rm + i];
        #pragma unroll
        for (int j = 0; j < 4; j++) {
            size_t idx = (size_t)b * CH * HWN + (size_t)(m0 + rm + i) * HWN + (n0 + rn + j);
            float v = acc[i][j] + bi;
            if (RES) v += res[idx];
            Y[idx] = v;
        }
    }
}

// ---------------- S = scale * Q^T K ----------------
// S[b,n,m] = scale * sum_c Q[b,c,n] * K[b,c,m]
__global__ void qk_kernel(const float* __restrict__ Q,
                          const float* __restrict__ K,
                          float* __restrict__ S) {
    const int BM = 64, BN = 64, BK = 16;
    const int b  = blockIdx.z;
    const int n0 = blockIdx.y * BM;   // rows of S
    const int m0 = blockIdx.x * BN;   // cols of S
    const float* Qb = Q + (size_t)b * CH * HWN;
    const float* Kb = K + (size_t)b * CH * HWN;

    __shared__ __align__(16) float As[BK][BM];
    __shared__ __align__(16) float Bs[BK][BN];

    const int tid = threadIdx.x;
    const int rm = (tid / 16) * 4;
    const int rn = (tid % 16) * 4;
    float acc[4][4] = {};

    for (int k0 = 0; k0 < CH; k0 += BK) {
        #pragma unroll
        for (int i = 0; i < 4; i++) {
            int e = tid + i * 256;
            int k = e / BM, mm = e % BM;
            As[k][mm] = Qb[(size_t)(k0 + k) * HWN + n0 + mm];
            Bs[k][mm] = Kb[(size_t)(k0 + k) * HWN + m0 + mm];
        }
        __syncthreads();
        #pragma unroll
        for (int k = 0; k < BK; k++) {
            float4 a4 = *reinterpret_cast<const float4*>(&As[k][rm]);
            float4 b4 = *reinterpret_cast<const float4*>(&Bs[k][rn]);
            float a[4] = {a4.x, a4.y, a4.z, a4.w};
            float bb[4] = {b4.x, b4.y, b4.z, b4.w};
            #pragma unroll
            for (int i = 0; i < 4; i++)
                #pragma unroll
                for (int j = 0; j < 4; j++)
                    acc[i][j] += a[i] * bb[j];
        }
        __syncthreads();
    }

    const float scale = 0.04419417382415922f; // 512^-0.5
    float* Sp = S + (size_t)b * HWN * HWN;
    #pragma unroll
    for (int i = 0; i < 4; i++)
        #pragma unroll
        for (int j = 0; j < 4; j++)
            Sp[(size_t)(n0 + rm + i) * HWN + (m0 + rn + j)] = acc[i][j] * scale;
}

// ---------------- row softmax over g_s ----------------
__global__ void softmax_kernel(float* __restrict__ S) {
    const size_t row = blockIdx.x;            // b*HWN + n
    float* p = S + row * (size_t)HWN;
    const int t = threadIdx.x;

    float vals[16];
    float mx = -INFINITY;
    #pragma unroll
    for (int i = 0; i < 16; i++) {
        vals[i] = p[t + i * 256];
        mx = fmaxf(mx, vals[i]);
    }
    __shared__ float sh[256];
    sh[t] = mx; __syncthreads();
    for (int o = 128; o > 0; o >>= 1) {
        if (t < o) sh[t] = fmaxf(sh[t], sh[t + o]);
        __syncthreads();
    }
    mx = sh[0];
    __syncthreads();

    float s = 0.f;
    #pragma unroll
    for (int i = 0; i < 16; i++) {
        vals[i] = expf(vals[i] - mx);
        s += vals[i];
    }
    sh[t] = s; __syncthreads();
    for (int o = 128; o > 0; o >>= 1) {
        if (t < o) sh[t] += sh[t + o];
        __syncthreads();
    }
    const float inv = 1.0f / sh[0];
    #pragma unroll
    for (int i = 0; i < 16; i++)
        p[t + i * 256] = vals[i] * inv;
}

// ---------------- O[b,c,n] = sum_m V[b,c,m] * P[b,n,m] ----------------
__global__ void av_kernel(const float* __restrict__ V,
                          const float* __restrict__ P,
                          float* __restrict__ O) {
    const int BM = 64, BN = 64, BK = 16;
    const int b  = blockIdx.z;
    const int c0 = blockIdx.y * BM;
    const int n0 = blockIdx.x * BN;
    const float* Vb = V + (size_t)b * CH * HWN;
    const float* Pb = P + (size_t)b * HWN * HWN;

    __shared__ __align__(16) float As[BK][BM];
    __shared__ __align__(16) float Bs[BK][BN];

    const int tid = threadIdx.x;
    const int rm = (tid / 16) * 4;
    const int rn = (tid % 16) * 4;
    float acc[4][4] = {};

    for (int k0 = 0; k0 < HWN; k0 += BK) {
        #pragma unroll
        for (int i = 0; i < 4; i++) {
            int e = tid + i * 256;
            int m = e / BK, k = e % BK;
            As[k][m] = Vb[(size_t)(c0 + m) * HWN + k0 + k];
        }
        #pragma unroll
        for (int i = 0; i < 4; i++) {
            int e = tid + i * 256;
            int nn = e / BK, k = e % BK;
            Bs[k][nn] = Pb[(size_t)(n0 + nn) * HWN + k0 + k];
        }
        __syncthreads();
        #pragma unroll
        for (int k = 0; k < BK; k++) {
            float4 a4 = *reinterpret_cast<const float4*>(&As[k][rm]);
            float4 b4 = *reinterpret_cast<const float4*>(&Bs[k][rn]);
            float a[4] = {a4.x, a4.y, a4.z, a4.w};
            float bb[4] = {b4.x, b4.y, b4.z, b4.w};
            #pragma unroll
            for (int i = 0; i < 4; i++)
                #pragma unroll
                for (int j = 0; j < 4; j++)
                    acc[i][j] += a[i] * bb[j];
        }
        __syncthreads();
    }

    #pragma unroll
    for (int i = 0; i < 4; i++)
        #pragma unroll
        for (int j = 0; j < 4; j++)
            O[(size_t)b * CH * HWN + (size_t)(c0 + rm + i) * HWN + (n0 + rn + j)] = acc[i][j];
}

// ---------------- launch ----------------
extern "C" void kernel_launch(void* const* d_in, const int* in_sizes, int n_in,
                              void* d_out, int out_size) {
    const float* x        = (const float*)d_in[0];
    const float* gn_gamma = (const float*)d_in[1];
    const float* gn_beta  = (const float*)d_in[2];
    const float* wq       = (const float*)d_in[3];
    const float* bq       = (const float*)d_in[4];
    const float* wk       = (const float*)d_in[5];
    const float* bk       = (const float*)d_in[6];
    const float* wv       = (const float*)d_in[7];
    const float* bv       = (const float*)d_in[8];
    const float* wo       = (const float*)d_in[9];
    const float* bo       = (const float*)d_in[10];
    float* out = (float*)d_out;

    // resolve scratch addresses (host query; not a stream op — capture-safe)
    float *ph, *pq, *pk, *pv, *po, *ps;
    cudaGetSymbolAddress((void**)&ph, g_h);
    cudaGetSymbolAddress((void**)&pq, g_q);
    cudaGetSymbolAddress((void**)&pk, g_k);
    cudaGetSymbolAddress((void**)&pv, g_v);
    cudaGetSymbolAddress((void**)&po, g_o);
    cudaGetSymbolAddress((void**)&ps, g_s);

    // 1) GroupNorm
    gn_kernel<<<BATCH * NGROUPS, 256>>>(x, gn_gamma, gn_beta, ph);

    // 2) q, k, v projections
    dim3 pg(HWN / 64, CH / 64, BATCH);
    proj_kernel<false><<<pg, 256>>>(wq, bq, ph, nullptr, pq);
    proj_kernel<false><<<pg, 256>>>(wk, bk, ph, nullptr, pk);
    proj_kernel<false><<<pg, 256>>>(wv, bv, ph, nullptr, pv);

    // 3) S = scale * Q^T K
    dim3 sg(HWN / 64, HWN / 64, BATCH);
    qk_kernel<<<sg, 256>>>(pq, pk, ps);

    // 4) softmax rows
    softmax_kernel<<<BATCH * HWN, 256>>>(ps);

    // 5) O = V P^T   (output in [c, n] layout)
    dim3 ag(HWN / 64, CH / 64, BATCH);
    av_kernel<<<ag, 256>>>(pv, ps, po);

    // 6) output projection + residual
    proj_kernel<true><<<pg, 256>>>(wo, bo, po, x, out);
}

// round 3
// speedup vs baseline: 4.0985x; 4.0985x over previous
#include <cuda_runtime.h>
#include <math.h>
#include <stdint.h>

#define BATCH 4
#define CH    512
#define HWN   4096
#define NGROUPS 32
#define CPG   16

// ---------------- scratch (device globals; allocation-free) ----------------
__device__ float g_h[(size_t)BATCH * CH * HWN];            // 32 MB
__device__ float g_q[(size_t)BATCH * CH * HWN];            // 32 MB
__device__ float g_k[(size_t)BATCH * CH * HWN];            // 32 MB
__device__ float g_v[(size_t)BATCH * CH * HWN];            // 32 MB
__device__ float g_o[(size_t)BATCH * CH * HWN];            // 32 MB
__device__ float g_s[(size_t)BATCH * HWN * HWN];           // 256 MB attention matrix

// ---------------- helpers ----------------
__device__ __forceinline__ uint32_t f2tf32(float f) {
    uint32_t u;
    asm("cvt.rna.tf32.f32 %0, %1;" : "=r"(u) : "f"(f));
    return u;
}

__device__ __forceinline__ void mma_tf32(float* d, const uint32_t* a, const uint32_t* b) {
    asm volatile(
        "mma.sync.aligned.m16n8k8.row.col.f32.tf32.tf32.f32 "
        "{%0,%1,%2,%3}, {%4,%5,%6,%7}, {%8,%9}, {%0,%1,%2,%3};"
        : "+f"(d[0]), "+f"(d[1]), "+f"(d[2]), "+f"(d[3])
        : "r"(a[0]), "r"(a[1]), "r"(a[2]), "r"(a[3]), "r"(b[0]), "r"(b[1]));
}

// ---------------- GroupNorm ----------------
__global__ void gn_kernel(const float* __restrict__ x,
                          const float* __restrict__ gamma,
                          const float* __restrict__ beta,
                          float* __restrict__ h) {
    const int b = blockIdx.x / NGROUPS;
    const int g = blockIdx.x % NGROUPS;
    const int n = CPG * HWN;
    const float* xp = x + ((size_t)b * CH + (size_t)g * CPG) * HWN;
    float*       hp = h + ((size_t)b * CH + (size_t)g * CPG) * HWN;

    float s = 0.f, ss = 0.f;
    for (int i = threadIdx.x; i < n; i += 256) {
        float v = xp[i];
        s += v; ss += v * v;
    }
    __shared__ float sh1[256], sh2[256];
    sh1[threadIdx.x] = s; sh2[threadIdx.x] = ss;
    __syncthreads();
    for (int o = 128; o > 0; o >>= 1) {
        if (threadIdx.x < o) {
            sh1[threadIdx.x] += sh1[threadIdx.x + o];
            sh2[threadIdx.x] += sh2[threadIdx.x + o];
        }
        __syncthreads();
    }
    const float mean = sh1[0] / (float)n;
    const float var  = sh2[0] / (float)n - mean * mean;
    const float inv  = rsqrtf(var + 1e-6f);

    for (int i = threadIdx.x; i < n; i += 256) {
        int c = g * CPG + i / HWN;
        hp[i] = (xp[i] - mean) * inv * gamma[c] + beta[c];
    }
}

// ---------------- TF32 tensor-core GEMM ----------------
// C[m,n] = op(A) * op(B)  with  op(A)[m,k], op(B)[k,n]
// ATRANS: A stored [K,M] (access A[k*lda+m]) else [M,K] (A[m*lda+k])
// BTRANS: B stored [N,K] (access B[n*ldb+k]) else [K,N] (B[k*ldb+n])
// EPI: 0 = plain, 1 = +bias[m], 2 = +bias[m]+res, 3 = *scale
#define TM 128
#define TN 128
#define TK 32

template<bool ATRANS, bool BTRANS, int EPI>
__global__ __launch_bounds__(256, 1)
void gemm_tf32(const float* __restrict__ Ag, const float* __restrict__ Bg,
               float* __restrict__ Cg,
               const float* __restrict__ bias, const float* __restrict__ res,
               int M, int N, int K, int lda, int ldb, int ldc,
               size_t strA, size_t strB, size_t strC, float scale)
{
    __shared__ uint32_t As[TK][TM + 4];
    __shared__ uint32_t Bs[TK][TN + 4];

    const int bz = blockIdx.z;
    const int m0 = blockIdx.y * TM;
    const int n0 = blockIdx.x * TN;
    const float* A = Ag + (size_t)bz * strA;
    const float* B = Bg + (size_t)bz * strB;
    float*       C = Cg + (size_t)bz * strC;
    const float* R = (EPI == 2) ? (res + (size_t)bz * strC) : nullptr;

    const int tid  = threadIdx.x;
    const int wid  = tid >> 5;
    const int lane = tid & 31;
    const int gid  = lane >> 2;
    const int tig  = lane & 3;
    const int wm   = (wid >> 2) * 64;   // warp m offset (0,64)
    const int wn   = (wid & 3) * 32;    // warp n offset (0..96)

    float acc[4][4][4] = {};
    float4 ra[4], rb[4];

    // ---- stage loaders (global -> regs) ----
    auto load_stage = [&](int k0) {
        #pragma unroll
        for (int i = 0; i < 4; i++) {
            int idx = tid + i * 256;
            if (ATRANS) {
                int m4 = idx & 31, k = idx >> 5;          // contiguous in m
                ra[i] = *reinterpret_cast<const float4*>(&A[(size_t)(k0 + k) * lda + m0 + m4 * 4]);
            } else {
                int m = idx & 127, kq = idx >> 7;         // contiguous in k
                ra[i] = *reinterpret_cast<const float4*>(&A[(size_t)(m0 + m) * lda + k0 + kq * 4]);
            }
            if (BTRANS) {
                int n = idx & 127, kq = idx >> 7;         // contiguous in k
                rb[i] = *reinterpret_cast<const float4*>(&B[(size_t)(n0 + n) * ldb + k0 + kq * 4]);
            } else {
                int n4 = idx & 31, k = idx >> 5;          // contiguous in n
                rb[i] = *reinterpret_cast<const float4*>(&B[(size_t)(k0 + k) * ldb + n0 + n4 * 4]);
            }
        }
    };
    auto store_stage = [&]() {
        #pragma unroll
        for (int i = 0; i < 4; i++) {
            int idx = tid + i * 256;
            float av[4] = {ra[i].x, ra[i].y, ra[i].z, ra[i].w};
            float bv[4] = {rb[i].x, rb[i].y, rb[i].z, rb[i].w};
            if (ATRANS) {
                int m4 = idx & 31, k = idx >> 5;
                #pragma unroll
                for (int j = 0; j < 4; j++) As[k][m4 * 4 + j] = f2tf32(av[j]);
            } else {
                int m = idx & 127, kq = idx >> 7;
                #pragma unroll
                for (int j = 0; j < 4; j++) As[kq * 4 + j][m] = f2tf32(av[j]);
            }
            if (BTRANS) {
                int n = idx & 127, kq = idx >> 7;
                #pragma unroll
                for (int j = 0; j < 4; j++) Bs[kq * 4 + j][n] = f2tf32(bv[j]);
            } else {
                int n4 = idx & 31, k = idx >> 5;
                #pragma unroll
                for (int j = 0; j < 4; j++) Bs[k][n4 * 4 + j] = f2tf32(bv[j]);
            }
        }
    };

    load_stage(0);
    for (int k0 = 0; k0 < K; k0 += TK) {
        store_stage();
        __syncthreads();
        if (k0 + TK < K) load_stage(k0 + TK);

        #pragma unroll
        for (int ks = 0; ks < 4; ks++) {
            const int kk = ks * 8;
            uint32_t af[4][4], bf[4][2];
            #pragma unroll
            for (int i = 0; i < 4; i++) {
                af[i][0] = As[kk + tig][wm + i * 16 + gid];
                af[i][1] = As[kk + tig][wm + i * 16 + gid + 8];
                af[i][2] = As[kk + tig + 4][wm + i * 16 + gid];
                af[i][3] = As[kk + tig + 4][wm + i * 16 + gid + 8];
            }
            #pragma unroll
            for (int j = 0; j < 4; j++) {
                bf[j][0] = Bs[kk + tig][wn + j * 8 + gid];
                bf[j][1] = Bs[kk + tig + 4][wn + j * 8 + gid];
            }
            #pragma unroll
            for (int i = 0; i < 4; i++)
                #pragma unroll
                for (int j = 0; j < 4; j++)
                    mma_tf32(acc[i][j], af[i], bf[j]);
        }
        __syncthreads();
    }

    // ---- epilogue ----
    #pragma unroll
    for (int i = 0; i < 4; i++) {
        const int r0 = m0 + wm + i * 16 + gid;
        float b0v = 0.f, b1v = 0.f;
        if (EPI == 1 || EPI == 2) { b0v = bias[r0]; b1v = bias[r0 + 8]; }
        #pragma unroll
        for (int j = 0; j < 4; j++) {
            const int c0 = n0 + wn + j * 8 + tig * 2;
            size_t i0 = (size_t)r0 * ldc + c0;
            size_t i1 = (size_t)(r0 + 8) * ldc + c0;
            float2 v0 = make_float2(acc[i][j][0], acc[i][j][1]);
            float2 v1 = make_float2(acc[i][j][2], acc[i][j][3]);
            if (EPI == 3) { v0.x *= scale; v0.y *= scale; v1.x *= scale; v1.y *= scale; }
            if (EPI == 1 || EPI == 2) { v0.x += b0v; v0.y += b0v; v1.x += b1v; v1.y += b1v; }
            if (EPI == 2) {
                float2 r0v = *reinterpret_cast<const float2*>(&R[i0]);
                float2 r1v = *reinterpret_cast<const float2*>(&R[i1]);
                v0.x += r0v.x; v0.y += r0v.y; v1.x += r1v.x; v1.y += r1v.y;
            }
            *reinterpret_cast<float2*>(&C[i0]) = v0;
            *reinterpret_cast<float2*>(&C[i1]) = v1;
        }
    }
}

// ---------------- row softmax ----------------
__global__ void softmax_kernel(float* __restrict__ S) {
    const size_t row = blockIdx.x;
    float* p = S + row * (size_t)HWN;
    const int t = threadIdx.x;

    float vals[16];
    float mx = -INFINITY;
    #pragma unroll
    for (int i = 0; i < 16; i++) {
        vals[i] = p[t + i * 256];
        mx = fmaxf(mx, vals[i]);
    }
    __shared__ float sh[256];
    sh[t] = mx; __syncthreads();
    for (int o = 128; o > 0; o >>= 1) {
        if (t < o) sh[t] = fmaxf(sh[t], sh[t + o]);
        __syncthreads();
    }
    mx = sh[0];
    __syncthreads();

    float s = 0.f;
    #pragma unroll
    for (int i = 0; i < 16; i++) {
        vals[i] = __expf(vals[i] - mx);
        s += vals[i];
    }
    sh[t] = s; __syncthreads();
    for (int o = 128; o > 0; o >>= 1) {
        if (t < o) sh[t] += sh[t + o];
        __syncthreads();
    }
    const float inv = 1.0f / sh[0];
    #pragma unroll
    for (int i = 0; i < 16; i++)
        p[t + i * 256] = vals[i] * inv;
}

// ---------------- launch ----------------
extern "C" void kernel_launch(void* const* d_in, const int* in_sizes, int n_in,
                              void* d_out, int out_size) {
    const float* x        = (const float*)d_in[0];
    const float* gn_gamma = (const float*)d_in[1];
    const float* gn_beta  = (const float*)d_in[2];
    const float* wq       = (const float*)d_in[3];
    const float* bq       = (const float*)d_in[4];
    const float* wk       = (const float*)d_in[5];
    const float* bk       = (const float*)d_in[6];
    const float* wv       = (const float*)d_in[7];
    const float* bv       = (const float*)d_in[8];
    const float* wo       = (const float*)d_in[9];
    const float* bo       = (const float*)d_in[10];
    float* out = (float*)d_out;

    float *ph, *pq, *pk, *pv, *po, *ps;
    cudaGetSymbolAddress((void**)&ph, g_h);
    cudaGetSymbolAddress((void**)&pq, g_q);
    cudaGetSymbolAddress((void**)&pk, g_k);
    cudaGetSymbolAddress((void**)&pv, g_v);
    cudaGetSymbolAddress((void**)&po, g_o);
    cudaGetSymbolAddress((void**)&ps, g_s);

    const size_t sCH = (size_t)CH * HWN;
    const size_t sSS = (size_t)HWN * HWN;
    const float scale = 0.04419417382415922f; // 512^-0.5

    // 1) GroupNorm
    gn_kernel<<<BATCH * NGROUPS, 256>>>(x, gn_gamma, gn_beta, ph);

    // 2) q,k,v projections: C[m,n] = W[m,k] H[k,n] + b
    dim3 pg(HWN / TN, CH / TM, BATCH);
    gemm_tf32<false, false, 1><<<pg, 256>>>(wq, ph, pq, bq, nullptr,
        CH, HWN, CH, CH, HWN, HWN, 0, sCH, sCH, 1.f);
    gemm_tf32<false, false, 1><<<pg, 256>>>(wk, ph, pk, bk, nullptr,
        CH, HWN, CH, CH, HWN, HWN, 0, sCH, sCH, 1.f);
    gemm_tf32<false, false, 1><<<pg, 256>>>(wv, ph, pv, bv, nullptr,
        CH, HWN, CH, CH, HWN, HWN, 0, sCH, sCH, 1.f);

    // 3) S[n,m] = scale * sum_c Q[c,n] K[c,m]   (A = Q, stored [K,M] -> ATRANS)
    dim3 sg(HWN / TN, HWN / TM, BATCH);
    gemm_tf32<true, false, 3><<<sg, 256>>>(pq, pk, ps, nullptr, nullptr,
        HWN, HWN, CH, HWN, HWN, HWN, sCH, sCH, sSS, scale);

    // 4) softmax rows
    softmax_kernel<<<BATCH * HWN, 256>>>(ps);

    // 5) O[c,n] = sum_m V[c,m] P[n,m]   (B = P stored [N,K] -> BTRANS)
    dim3 ag(HWN / TN, CH / TM, BATCH);
    gemm_tf32<false, true, 0><<<ag, 256>>>(pv, ps, po, nullptr, nullptr,
        CH, HWN, HWN, HWN, HWN, HWN, sCH, sSS, sCH, 1.f);

    // 6) out projection + bias + residual
    gemm_tf32<false, false, 2><<<pg, 256>>>(wo, po, out, bo, x,
        CH, HWN, CH, CH, HWN, HWN, 0, sCH, sCH, 1.f);
}

// round 4
// speedup vs baseline: 8.7196x; 2.1275x over previous
#include <cuda_runtime.h>
#include <math.h>
#include <stdint.h>

#define BATCH 4
#define CH    512
#define HWN   4096
#define NGROUPS 32
#define CPG   16

#define TM 128
#define TN 128
#define TK 32
#define STAGES 3

// ---------------- scratch (device globals; allocation-free) ----------------
__device__ float g_h[(size_t)BATCH * CH * HWN];
__device__ float g_q[(size_t)BATCH * CH * HWN];
__device__ float g_k[(size_t)BATCH * CH * HWN];
__device__ float g_v[(size_t)BATCH * CH * HWN];
__device__ float g_o[(size_t)BATCH * CH * HWN];
__device__ float g_s[(size_t)BATCH * HWN * HWN];

// ---------------- helpers ----------------
__device__ __forceinline__ uint32_t smem_u32(const void* p) {
    return (uint32_t)__cvta_generic_to_shared(p);
}
__device__ __forceinline__ void cp16(uint32_t dst, const float* src) {
    asm volatile("cp.async.cg.shared.global [%0], [%1], 16;\n" :: "r"(dst), "l"(src));
}
__device__ __forceinline__ void cp_commit() {
    asm volatile("cp.async.commit_group;\n");
}
template<int N> __device__ __forceinline__ void cp_wait() {
    asm volatile("cp.async.wait_group %0;\n" :: "n"(N));
}
__device__ __forceinline__ void mma_tf32(float* d, const uint32_t* a, const uint32_t* b) {
    asm volatile(
        "mma.sync.aligned.m16n8k8.row.col.f32.tf32.tf32.f32 "
        "{%0,%1,%2,%3}, {%4,%5,%6,%7}, {%8,%9}, {%0,%1,%2,%3};"
        : "+f"(d[0]), "+f"(d[1]), "+f"(d[2]), "+f"(d[3])
        : "r"(a[0]), "r"(a[1]), "r"(a[2]), "r"(a[3]), "r"(b[0]), "r"(b[1]));
}
__device__ __forceinline__ uint32_t fbits(float f) { return __float_as_uint(f); }

// ---------------- GroupNorm ----------------
__global__ void gn_kernel(const float* __restrict__ x,
                          const float* __restrict__ gamma,
                          const float* __restrict__ beta,
                          float* __restrict__ h) {
    const int b = blockIdx.x / NGROUPS;
    const int g = blockIdx.x % NGROUPS;
    const int n = CPG * HWN;
    const float* xp = x + ((size_t)b * CH + (size_t)g * CPG) * HWN;
    float*       hp = h + ((size_t)b * CH + (size_t)g * CPG) * HWN;

    float s = 0.f, ss = 0.f;
    for (int i = threadIdx.x; i < n; i += 256) {
        float v = xp[i];
        s += v; ss += v * v;
    }
    __shared__ float sh1[256], sh2[256];
    sh1[threadIdx.x] = s; sh2[threadIdx.x] = ss;
    __syncthreads();
    for (int o = 128; o > 0; o >>= 1) {
        if (threadIdx.x < o) {
            sh1[threadIdx.x] += sh1[threadIdx.x + o];
            sh2[threadIdx.x] += sh2[threadIdx.x + o];
        }
        __syncthreads();
    }
    const float mean = sh1[0] / (float)n;
    const float var  = sh2[0] / (float)n - mean * mean;
    const float inv  = rsqrtf(var + 1e-6f);

    for (int i = threadIdx.x; i < n; i += 256) {
        int c = g * CPG + i / HWN;
        hp[i] = (xp[i] - mean) * inv * gamma[c] + beta[c];
    }
}

// ---------------- TF32 tensor-core GEMM, 3-stage cp.async pipeline ----------
// C[m,n] = op(A)*op(B); ATRANS: A stored [K,M]; BTRANS: B stored [N,K]
// EPI: 0 plain, 1 +bias, 2 +bias+res, 3 *scale
template<bool ATRANS, bool BTRANS, int EPI>
__global__ __launch_bounds__(256)
void gemm_tf32(const float* __restrict__ Ag, const float* __restrict__ Bg,
               float* __restrict__ Cg,
               const float* __restrict__ bias, const float* __restrict__ res,
               int K, int lda, int ldb, int ldc,
               size_t strA, size_t strB, size_t strC, float scale)
{
    extern __shared__ float smem[];
    // k-contiguous operand: [mn][TK+4]; mn-contiguous operand: [k][TMN+8]
    constexpr int SA = ATRANS ? (TM + 8) : (TK + 4);   // row stride of A tile
    constexpr int SB = BTRANS ? (TK + 4) : (TN + 8);   // row stride of B tile
    constexpr int SZA = ATRANS ? TK * SA : TM * SA;
    constexpr int SZB = BTRANS ? TN * SB : TK * SB;
    constexpr int STG = SZA + SZB;

    const int bz = blockIdx.z;
    const int m0 = blockIdx.y * TM;
    const int n0 = blockIdx.x * TN;
    const float* A = Ag + (size_t)bz * strA;
    const float* B = Bg + (size_t)bz * strB;
    float*       C = Cg + (size_t)bz * strC;
    const float* R = (EPI == 2) ? (res + (size_t)bz * strC) : nullptr;

    const int tid  = threadIdx.x;
    const int wid  = tid >> 5;
    const int lane = tid & 31;
    const int gid  = lane >> 2;
    const int tig  = lane & 3;
    const int wm   = (wid >> 2) * 64;
    const int wn   = (wid & 3) * 32;

    auto copy_tile = [&](int kt, int st) {
        float* as = smem + st * STG;
        float* bs = as + SZA;
        const int k0 = kt * TK;
        #pragma unroll
        for (int i = 0; i < 4; i++) {
            int idx = tid + i * 256;
            if (ATRANS) {           // A[K,M], m contiguous
                int k = idx >> 5, c = idx & 31;
                cp16(smem_u32(as + k * SA + c * 4), &A[(size_t)(k0 + k) * lda + m0 + c * 4]);
            } else {                // A[M,K], k contiguous
                int m = idx >> 3, c = idx & 7;
                cp16(smem_u32(as + m * SA + c * 4), &A[(size_t)(m0 + m) * lda + k0 + c * 4]);
            }
        }
        #pragma unroll
        for (int i = 0; i < 4; i++) {
            int idx = tid + i * 256;
            if (BTRANS) {           // B[N,K], k contiguous
                int n = idx >> 3, c = idx & 7;
                cp16(smem_u32(bs + n * SB + c * 4), &B[(size_t)(n0 + n) * ldb + k0 + c * 4]);
            } else {                // B[K,N], n contiguous
                int k = idx >> 5, c = idx & 31;
                cp16(smem_u32(bs + k * SB + c * 4), &B[(size_t)(k0 + k) * ldb + n0 + c * 4]);
            }
        }
    };

    float acc[4][4][4] = {};
    const int KT = K / TK;

    copy_tile(0, 0); cp_commit();
    copy_tile(1, 1); cp_commit();

    for (int kt = 0; kt < KT; kt++) {
        cp_wait<1>();
        __syncthreads();
        if (kt + 2 < KT) copy_tile(kt + 2, (kt + 2) % STAGES);
        cp_commit();

        const float* as = smem + (kt % STAGES) * STG;
        const float* bs = as + SZA;

        #pragma unroll
        for (int ks = 0; ks < 4; ks++) {
            const int kk = ks * 8;
            uint32_t af[4][4], bf[4][2];
            #pragma unroll
            for (int i = 0; i < 4; i++) {
                const int m = wm + i * 16 + gid;
                if (ATRANS) {
                    af[i][0] = fbits(as[(kk + tig) * SA + m]);
                    af[i][1] = fbits(as[(kk + tig) * SA + m + 8]);
                    af[i][2] = fbits(as[(kk + tig + 4) * SA + m]);
                    af[i][3] = fbits(as[(kk + tig + 4) * SA + m + 8]);
                } else {
                    af[i][0] = fbits(as[m * SA + kk + tig]);
                    af[i][1] = fbits(as[(m + 8) * SA + kk + tig]);
                    af[i][2] = fbits(as[m * SA + kk + tig + 4]);
                    af[i][3] = fbits(as[(m + 8) * SA + kk + tig + 4]);
                }
            }
            #pragma unroll
            for (int j = 0; j < 4; j++) {
                const int n = wn + j * 8 + gid;
                if (BTRANS) {
                    bf[j][0] = fbits(bs[n * SB + kk + tig]);
                    bf[j][1] = fbits(bs[n * SB + kk + tig + 4]);
                } else {
                    bf[j][0] = fbits(bs[(kk + tig) * SB + n]);
                    bf[j][1] = fbits(bs[(kk + tig + 4) * SB + n]);
                }
            }
            #pragma unroll
            for (int i = 0; i < 4; i++)
                #pragma unroll
                for (int j = 0; j < 4; j++)
                    mma_tf32(acc[i][j], af[i], bf[j]);
        }
    }

    __syncthreads();

    // ---- epilogue ----
    #pragma unroll
    for (int i = 0; i < 4; i++) {
        const int r0 = m0 + wm + i * 16 + gid;
        float b0v = 0.f, b1v = 0.f;
        if (EPI == 1 || EPI == 2) { b0v = bias[r0]; b1v = bias[r0 + 8]; }
        #pragma unroll
        for (int j = 0; j < 4; j++) {
            const int c0 = n0 + wn + j * 8 + tig * 2;
            size_t i0 = (size_t)r0 * ldc + c0;
            size_t i1 = (size_t)(r0 + 8) * ldc + c0;
            float2 v0 = make_float2(acc[i][j][0], acc[i][j][1]);
            float2 v1 = make_float2(acc[i][j][2], acc[i][j][3]);
            if (EPI == 3) { v0.x *= scale; v0.y *= scale; v1.x *= scale; v1.y *= scale; }
            if (EPI == 1 || EPI == 2) { v0.x += b0v; v0.y += b0v; v1.x += b1v; v1.y += b1v; }
            if (EPI == 2) {
                float2 r0v = *reinterpret_cast<const float2*>(&R[i0]);
                float2 r1v = *reinterpret_cast<const float2*>(&R[i1]);
                v0.x += r0v.x; v0.y += r0v.y; v1.x += r1v.x; v1.y += r1v.y;
            }
            *reinterpret_cast<float2*>(&C[i0]) = v0;
            *reinterpret_cast<float2*>(&C[i1]) = v1;
        }
    }
}

// ---------------- row softmax (vectorized) ----------------
__global__ void softmax_kernel(float* __restrict__ S) {
    const size_t row = blockIdx.x;
    float4* p = reinterpret_cast<float4*>(S + row * (size_t)HWN);
    const int t = threadIdx.x;

    float4 v[4];
    float mx = -INFINITY;
    #pragma unroll
    for (int i = 0; i < 4; i++) {
        v[i] = p[t + i * 256];
        mx = fmaxf(mx, fmaxf(fmaxf(v[i].x, v[i].y), fmaxf(v[i].z, v[i].w)));
    }
    __shared__ float sh[256];
    sh[t] = mx; __syncthreads();
    for (int o = 128; o > 0; o >>= 1) {
        if (t < o) sh[t] = fmaxf(sh[t], sh[t + o]);
        __syncthreads();
    }
    mx = sh[0];
    __syncthreads();

    float s = 0.f;
    #pragma unroll
    for (int i = 0; i < 4; i++) {
        v[i].x = __expf(v[i].x - mx); v[i].y = __expf(v[i].y - mx);
        v[i].z = __expf(v[i].z - mx); v[i].w = __expf(v[i].w - mx);
        s += v[i].x + v[i].y + v[i].z + v[i].w;
    }
    sh[t] = s; __syncthreads();
    for (int o = 128; o > 0; o >>= 1) {
        if (t < o) sh[t] += sh[t + o];
        __syncthreads();
    }
    const float inv = 1.0f / sh[0];
    #pragma unroll
    for (int i = 0; i < 4; i++) {
        v[i].x *= inv; v[i].y *= inv; v[i].z *= inv; v[i].w *= inv;
        p[t + i * 256] = v[i];
    }
}

// ---------------- launch ----------------
extern "C" void kernel_launch(void* const* d_in, const int* in_sizes, int n_in,
                              void* d_out, int out_size) {
    const float* x        = (const float*)d_in[0];
    const float* gn_gamma = (const float*)d_in[1];
    const float* gn_beta  = (const float*)d_in[2];
    const float* wq       = (const float*)d_in[3];
    const float* bq       = (const float*)d_in[4];
    const float* wk       = (const float*)d_in[5];
    const float* bk       = (const float*)d_in[6];
    const float* wv       = (const float*)d_in[7];
    const float* bv       = (const float*)d_in[8];
    const float* wo       = (const float*)d_in[9];
    const float* bo       = (const float*)d_in[10];
    float* out = (float*)d_out;

    float *ph, *pq, *pk, *pv, *po, *ps;
    cudaGetSymbolAddress((void**)&ph, g_h);
    cudaGetSymbolAddress((void**)&pq, g_q);
    cudaGetSymbolAddress((void**)&pk, g_k);
    cudaGetSymbolAddress((void**)&pv, g_v);
    cudaGetSymbolAddress((void**)&po, g_o);
    cudaGetSymbolAddress((void**)&ps, g_s);

    const size_t sCH = (size_t)CH * HWN;
    const size_t sSS = (size_t)HWN * HWN;
    const float scale = 0.04419417382415922f; // 512^-0.5

    // dynamic smem sizes per instantiation
    const int smem_ff = STAGES * (TM * (TK + 4) + TK * (TN + 8)) * 4; // proj
    const int smem_tf = STAGES * (TK * (TM + 8) + TK * (TN + 8)) * 4; // qk
    const int smem_ft = STAGES * (TM * (TK + 4) + TN * (TK + 4)) * 4; // av

    cudaFuncSetAttribute(gemm_tf32<false, false, 1>, cudaFuncAttributeMaxDynamicSharedMemorySize, smem_ff);
    cudaFuncSetAttribute(gemm_tf32<false, false, 2>, cudaFuncAttributeMaxDynamicSharedMemorySize, smem_ff);
    cudaFuncSetAttribute(gemm_tf32<true,  false, 3>, cudaFuncAttributeMaxDynamicSharedMemorySize, smem_tf);
    cudaFuncSetAttribute(gemm_tf32<false, true,  0>, cudaFuncAttributeMaxDynamicSharedMemorySize, smem_ft);

    // 1) GroupNorm
    gn_kernel<<<BATCH * NGROUPS, 256>>>(x, gn_gamma, gn_beta, ph);

    // 2) q,k,v projections
    dim3 pg(HWN / TN, CH / TM, BATCH);
    gemm_tf32<false, false, 1><<<pg, 256, smem_ff>>>(wq, ph, pq, bq, nullptr,
        CH, CH, HWN, HWN, 0, sCH, sCH, 1.f);
    gemm_tf32<false, false, 1><<<pg, 256, smem_ff>>>(wk, ph, pk, bk, nullptr,
        CH, CH, HWN, HWN, 0, sCH, sCH, 1.f);
    gemm_tf32<false, false, 1><<<pg, 256, smem_ff>>>(wv, ph, pv, bv, nullptr,
        CH, CH, HWN, HWN, 0, sCH, sCH, 1.f);

    // 3) S[n,m] = scale * Q^T K
    dim3 sg(HWN / TN, HWN / TM, BATCH);
    gemm_tf32<true, false, 3><<<sg, 256, smem_tf>>>(pq, pk, ps, nullptr, nullptr,
        CH, HWN, HWN, HWN, sCH, sCH, sSS, scale);

    // 4) softmax rows
    softmax_kernel<<<BATCH * HWN, 256>>>(ps);

    // 5) O[c,n] = sum_m V[c,m] P[n,m]
    dim3 ag(HWN / TN, CH / TM, BATCH);
    gemm_tf32<false, true, 0><<<ag, 256, smem_ft>>>(pv, ps, po, nullptr, nullptr,
        HWN, HWN, HWN, HWN, sCH, sSS, sCH, 1.f);

    // 6) out projection + bias + residual
    gemm_tf32<false, false, 2><<<pg, 256, smem_ff>>>(wo, po, out, bo, x,
        CH, CH, HWN, HWN, 0, sCH, sCH, 1.f);
}

// round 5
// speedup vs baseline: 9.2360x; 1.0592x over previous
#include <cuda_runtime.h>
#include <math.h>
#include <stdint.h>

#define BATCH 4
#define CH    512
#define HWN   4096
#define NGROUPS 32
#define CPG   16

#define TM 128
#define TN 128
#define TK 32
#define STAGES 3

// ---------------- scratch (device globals; allocation-free) ----------------
__device__ float g_h[(size_t)BATCH * CH * HWN];
__device__ float g_q[(size_t)BATCH * CH * HWN];
__device__ float g_k[(size_t)BATCH * CH * HWN];
__device__ float g_v[(size_t)BATCH * CH * HWN];
__device__ float g_o[(size_t)BATCH * CH * HWN];
__device__ float g_s[(size_t)BATCH * HWN * HWN];   // holds unnormalized exp(S)
__device__ float g_l[(size_t)BATCH * HWN];         // row sums of exp(S)

// ---------------- helpers ----------------
__device__ __forceinline__ uint32_t smem_u32(const void* p) {
    return (uint32_t)__cvta_generic_to_shared(p);
}
__device__ __forceinline__ void cp16(uint32_t dst, const float* src) {
    asm volatile("cp.async.cg.shared.global [%0], [%1], 16;\n" :: "r"(dst), "l"(src));
}
__device__ __forceinline__ void cp_commit() {
    asm volatile("cp.async.commit_group;\n");
}
template<int N> __device__ __forceinline__ void cp_wait() {
    asm volatile("cp.async.wait_group %0;\n" :: "n"(N));
}
__device__ __forceinline__ void mma_tf32(float* d, const uint32_t* a, const uint32_t* b) {
    asm volatile(
        "mma.sync.aligned.m16n8k8.row.col.f32.tf32.tf32.f32 "
        "{%0,%1,%2,%3}, {%4,%5,%6,%7}, {%8,%9}, {%0,%1,%2,%3};"
        : "+f"(d[0]), "+f"(d[1]), "+f"(d[2]), "+f"(d[3])
        : "r"(a[0]), "r"(a[1]), "r"(a[2]), "r"(a[3]), "r"(b[0]), "r"(b[1]));
}
__device__ __forceinline__ uint32_t fbits(float f) { return __float_as_uint(f); }

// ---------------- GroupNorm ----------------
__global__ void gn_kernel(const float* __restrict__ x,
                          const float* __restrict__ gamma,
                          const float* __restrict__ beta,
                          float* __restrict__ h) {
    const int b = blockIdx.x / NGROUPS;
    const int g = blockIdx.x % NGROUPS;
    const int n = CPG * HWN;
    const float* xp = x + ((size_t)b * CH + (size_t)g * CPG) * HWN;
    float*       hp = h + ((size_t)b * CH + (size_t)g * CPG) * HWN;

    float s = 0.f, ss = 0.f;
    for (int i = threadIdx.x; i < n; i += 256) {
        float v = xp[i];
        s += v; ss += v * v;
    }
    __shared__ float sh1[256], sh2[256];
    sh1[threadIdx.x] = s; sh2[threadIdx.x] = ss;
    __syncthreads();
    for (int o = 128; o > 0; o >>= 1) {
        if (threadIdx.x < o) {
            sh1[threadIdx.x] += sh1[threadIdx.x + o];
            sh2[threadIdx.x] += sh2[threadIdx.x + o];
        }
        __syncthreads();
    }
    const float mean = sh1[0] / (float)n;
    const float var  = sh2[0] / (float)n - mean * mean;
    const float inv  = rsqrtf(var + 1e-6f);

    for (int i = threadIdx.x; i < n; i += 256) {
        int c = g * CPG + i / HWN;
        hp[i] = (xp[i] - mean) * inv * gamma[c] + beta[c];
    }
}

// ---------------- TF32 tensor-core GEMM, 3-stage cp.async pipeline ----------
// C[m,n] = op(A)*op(B); ATRANS: A stored [K,M]; BTRANS: B stored [N,K]
// EPI: 0 plain, 1 +bias, 2 +bias+res,
//      4 exp(scale*acc) + atomic row sums into Lsum[m],
//      5 divide column n by Lsum[n] (softmax normalization)
template<bool ATRANS, bool BTRANS, int EPI>
__global__ __launch_bounds__(256)
void gemm_tf32(const float* __restrict__ Ag, const float* __restrict__ Bg,
               float* __restrict__ Cg,
               const float* __restrict__ bias, const float* __restrict__ res,
               float* __restrict__ Lsum,
               int K, int lda, int ldb, int ldc,
               size_t strA, size_t strB, size_t strC, float scale)
{
    extern __shared__ float smem[];
    constexpr int SA = ATRANS ? (TM + 8) : (TK + 4);
    constexpr int SB = BTRANS ? (TK + 4) : (TN + 8);
    constexpr int SZA = ATRANS ? TK * SA : TM * SA;
    constexpr int SZB = BTRANS ? TN * SB : TK * SB;
    constexpr int STG = SZA + SZB;

    const int bz = blockIdx.z;
    const int m0 = blockIdx.y * TM;
    const int n0 = blockIdx.x * TN;
    const float* A = Ag + (size_t)bz * strA;
    const float* B = Bg + (size_t)bz * strB;
    float*       C = Cg + (size_t)bz * strC;
    const float* R = (EPI == 2) ? (res + (size_t)bz * strC) : nullptr;
    float* L = (EPI == 4 || EPI == 5) ? (Lsum + (size_t)bz * HWN) : nullptr;

    const int tid  = threadIdx.x;
    const int wid  = tid >> 5;
    const int lane = tid & 31;
    const int gid  = lane >> 2;
    const int tig  = lane & 3;
    const int wm   = (wid >> 2) * 64;
    const int wn   = (wid & 3) * 32;

    auto copy_tile = [&](int kt, int st) {
        float* as = smem + st * STG;
        float* bs = as + SZA;
        const int k0 = kt * TK;
        #pragma unroll
        for (int i = 0; i < 4; i++) {
            int idx = tid + i * 256;
            if (ATRANS) {
                int k = idx >> 5, c = idx & 31;
                cp16(smem_u32(as + k * SA + c * 4), &A[(size_t)(k0 + k) * lda + m0 + c * 4]);
            } else {
                int m = idx >> 3, c = idx & 7;
                cp16(smem_u32(as + m * SA + c * 4), &A[(size_t)(m0 + m) * lda + k0 + c * 4]);
            }
        }
        #pragma unroll
        for (int i = 0; i < 4; i++) {
            int idx = tid + i * 256;
            if (BTRANS) {
                int n = idx >> 3, c = idx & 7;
                cp16(smem_u32(bs + n * SB + c * 4), &B[(size_t)(n0 + n) * ldb + k0 + c * 4]);
            } else {
                int k = idx >> 5, c = idx & 31;
                cp16(smem_u32(bs + k * SB + c * 4), &B[(size_t)(k0 + k) * ldb + n0 + c * 4]);
            }
        }
    };

    float acc[4][4][4] = {};
    const int KT = K / TK;

    copy_tile(0, 0); cp_commit();
    copy_tile(1, 1); cp_commit();

    for (int kt = 0; kt < KT; kt++) {
        cp_wait<1>();
        __syncthreads();
        if (kt + 2 < KT) copy_tile(kt + 2, (kt + 2) % STAGES);
        cp_commit();

        const float* as = smem + (kt % STAGES) * STG;
        const float* bs = as + SZA;

        #pragma unroll
        for (int ks = 0; ks < 4; ks++) {
            const int kk = ks * 8;
            uint32_t af[4][4], bf[4][2];
            #pragma unroll
            for (int i = 0; i < 4; i++) {
                const int m = wm + i * 16 + gid;
                if (ATRANS) {
                    af[i][0] = fbits(as[(kk + tig) * SA + m]);
                    af[i][1] = fbits(as[(kk + tig) * SA + m + 8]);
                    af[i][2] = fbits(as[(kk + tig + 4) * SA + m]);
                    af[i][3] = fbits(as[(kk + tig + 4) * SA + m + 8]);
                } else {
                    af[i][0] = fbits(as[m * SA + kk + tig]);
                    af[i][1] = fbits(as[(m + 8) * SA + kk + tig]);
                    af[i][2] = fbits(as[m * SA + kk + tig + 4]);
                    af[i][3] = fbits(as[(m + 8) * SA + kk + tig + 4]);
                }
            }
            #pragma unroll
            for (int j = 0; j < 4; j++) {
                const int n = wn + j * 8 + gid;
                if (BTRANS) {
                    bf[j][0] = fbits(bs[n * SB + kk + tig]);
                    bf[j][1] = fbits(bs[n * SB + kk + tig + 4]);
                } else {
                    bf[j][0] = fbits(bs[(kk + tig) * SB + n]);
                    bf[j][1] = fbits(bs[(kk + tig + 4) * SB + n]);
                }
            }
            #pragma unroll
            for (int i = 0; i < 4; i++)
                #pragma unroll
                for (int j = 0; j < 4; j++)
                    mma_tf32(acc[i][j], af[i], bf[j]);
        }
    }

    __syncthreads();

    // ---- epilogue ----
    #pragma unroll
    for (int i = 0; i < 4; i++) {
        const int r0 = m0 + wm + i * 16 + gid;
        float b0v = 0.f, b1v = 0.f;
        if (EPI == 1 || EPI == 2) { b0v = bias[r0]; b1v = bias[r0 + 8]; }
        float rsum0 = 0.f, rsum1 = 0.f;
        #pragma unroll
        for (int j = 0; j < 4; j++) {
            const int c0 = n0 + wn + j * 8 + tig * 2;
            size_t i0 = (size_t)r0 * ldc + c0;
            size_t i1 = (size_t)(r0 + 8) * ldc + c0;
            float2 v0 = make_float2(acc[i][j][0], acc[i][j][1]);
            float2 v1 = make_float2(acc[i][j][2], acc[i][j][3]);
            if (EPI == 1 || EPI == 2) { v0.x += b0v; v0.y += b0v; v1.x += b1v; v1.y += b1v; }
            if (EPI == 2) {
                float2 r0v = *reinterpret_cast<const float2*>(&R[i0]);
                float2 r1v = *reinterpret_cast<const float2*>(&R[i1]);
                v0.x += r0v.x; v0.y += r0v.y; v1.x += r1v.x; v1.y += r1v.y;
            }
            if (EPI == 4) {
                v0.x = __expf(v0.x * scale); v0.y = __expf(v0.y * scale);
                v1.x = __expf(v1.x * scale); v1.y = __expf(v1.y * scale);
                rsum0 += v0.x + v0.y;
                rsum1 += v1.x + v1.y;
            }
            if (EPI == 5) {
                float l0 = L[c0], l1 = L[c0 + 1];
                v0.x /= l0; v0.y /= l1;
                v1.x /= l0; v1.y /= l1;
            }
            *reinterpret_cast<float2*>(&C[i0]) = v0;
            *reinterpret_cast<float2*>(&C[i1]) = v1;
        }
        if (EPI == 4) {
            // lanes {gid*4 + tig} share rows r0/r0+8 across tig: butterfly over low 2 bits
            rsum0 += __shfl_xor_sync(0xffffffffu, rsum0, 1);
            rsum0 += __shfl_xor_sync(0xffffffffu, rsum0, 2);
            rsum1 += __shfl_xor_sync(0xffffffffu, rsum1, 1);
            rsum1 += __shfl_xor_sync(0xffffffffu, rsum1, 2);
            if (tig == 0) {
                atomicAdd(&L[r0], rsum0);
                atomicAdd(&L[r0 + 8], rsum1);
            }
        }
    }
}

// ---------------- launch ----------------
extern "C" void kernel_launch(void* const* d_in, const int* in_sizes, int n_in,
                              void* d_out, int out_size) {
    const float* x        = (const float*)d_in[0];
    const float* gn_gamma = (const float*)d_in[1];
    const float* gn_beta  = (const float*)d_in[2];
    const float* wq       = (const float*)d_in[3];
    const float* bq       = (const float*)d_in[4];
    const float* wk       = (const float*)d_in[5];
    const float* bk       = (const float*)d_in[6];
    const float* wv       = (const float*)d_in[7];
    const float* bv       = (const float*)d_in[8];
    const float* wo       = (const float*)d_in[9];
    const float* bo       = (const float*)d_in[10];
    float* out = (float*)d_out;

    float *ph, *pq, *pk, *pv, *po, *ps, *pl;
    cudaGetSymbolAddress((void**)&ph, g_h);
    cudaGetSymbolAddress((void**)&pq, g_q);
    cudaGetSymbolAddress((void**)&pk, g_k);
    cudaGetSymbolAddress((void**)&pv, g_v);
    cudaGetSymbolAddress((void**)&po, g_o);
    cudaGetSymbolAddress((void**)&ps, g_s);
    cudaGetSymbolAddress((void**)&pl, g_l);

    const size_t sCH = (size_t)CH * HWN;
    const size_t sSS = (size_t)HWN * HWN;
    const float scale = 0.04419417382415922f; // 512^-0.5

    const int smem_ff = STAGES * (TM * (TK + 4) + TK * (TN + 8)) * 4;
    const int smem_tf = STAGES * (TK * (TM + 8) + TK * (TN + 8)) * 4;
    const int smem_ft = STAGES * (TM * (TK + 4) + TN * (TK + 4)) * 4;

    cudaFuncSetAttribute(gemm_tf32<false, false, 1>, cudaFuncAttributeMaxDynamicSharedMemorySize, smem_ff);
    cudaFuncSetAttribute(gemm_tf32<false, false, 2>, cudaFuncAttributeMaxDynamicSharedMemorySize, smem_ff);
    cudaFuncSetAttribute(gemm_tf32<true,  false, 4>, cudaFuncAttributeMaxDynamicSharedMemorySize, smem_tf);
    cudaFuncSetAttribute(gemm_tf32<false, true,  5>, cudaFuncAttributeMaxDynamicSharedMemorySize, smem_ft);

    // 1) GroupNorm
    gn_kernel<<<BATCH * NGROUPS, 256>>>(x, gn_gamma, gn_beta, ph);

    // 2) q,k,v projections
    dim3 pg(HWN / TN, CH / TM, BATCH);
    gemm_tf32<false, false, 1><<<pg, 256, smem_ff>>>(wq, ph, pq, bq, nullptr, nullptr,
        CH, CH, HWN, HWN, 0, sCH, sCH, 1.f);
    gemm_tf32<false, false, 1><<<pg, 256, smem_ff>>>(wk, ph, pk, bk, nullptr, nullptr,
        CH, CH, HWN, HWN, 0, sCH, sCH, 1.f);
    gemm_tf32<false, false, 1><<<pg, 256, smem_ff>>>(wv, ph, pv, bv, nullptr, nullptr,
        CH, CH, HWN, HWN, 0, sCH, sCH, 1.f);

    // zero row sums (graph-capturable memset node)
    cudaMemsetAsync(pl, 0, (size_t)BATCH * HWN * sizeof(float));

    // 3) P~[n,m] = exp(scale * Q^T K), row sums -> g_l  (no max-sub: |S| <~ 6)
    dim3 sg(HWN / TN, HWN / TM, BATCH);
    gemm_tf32<true, false, 4><<<sg, 256, smem_tf>>>(pq, pk, ps, nullptr, nullptr, pl,
        CH, HWN, HWN, HWN, sCH, sCH, sSS, scale);

    // 4) O[c,n] = (sum_m V[c,m] P~[n,m]) / l[n]
    dim3 ag(HWN / TN, CH / TM, BATCH);
    gemm_tf32<false, true, 5><<<ag, 256, smem_ft>>>(pv, ps, po, nullptr, nullptr, pl,
        HWN, HWN, HWN, HWN, sCH, sSS, sCH, 1.f);

    // 5) out projection + bias + residual
    gemm_tf32<false, false, 2><<<pg, 256, smem_ff>>>(wo, po, out, bo, x, nullptr,
        CH, CH, HWN, HWN, 0, sCH, sCH, 1.f);
}

// round 6
// speedup vs baseline: 16.2029x; 1.7543x over previous
#include <cuda_runtime.h>
#include <cuda_fp16.h>
#include <math.h>
#include <stdint.h>

#define BATCH 4
#define CH    512
#define HWN   4096
#define NGROUPS 32
#define CPG   16

#define TM 128
#define TN 128
#define TK 32
#define STAGES 3

// ---------------- scratch (device globals; allocation-free) ----------------
__device__ __half g_h[(size_t)BATCH * CH * HWN];
__device__ __half g_q[(size_t)BATCH * CH * HWN];
__device__ __half g_k[(size_t)BATCH * CH * HWN];
__device__ __half g_v[(size_t)BATCH * CH * HWN];
__device__ __half g_o[(size_t)BATCH * CH * HWN];
__device__ __half g_s[(size_t)BATCH * HWN * HWN];   // unnormalized exp(S), fp16
__device__ float  g_l[(size_t)BATCH * HWN];         // row sums (fp32)
__device__ __half g_w[4 * CH * CH];                 // fp16 weights: q,k,v,o

// ---------------- helpers ----------------
__device__ __forceinline__ uint32_t smem_u32(const void* p) {
    return (uint32_t)__cvta_generic_to_shared(p);
}
__device__ __forceinline__ void cp16(uint32_t dst, const void* src) {
    asm volatile("cp.async.cg.shared.global [%0], [%1], 16;\n" :: "r"(dst), "l"(src));
}
__device__ __forceinline__ void cp_commit() {
    asm volatile("cp.async.commit_group;\n");
}
template<int N> __device__ __forceinline__ void cp_wait() {
    asm volatile("cp.async.wait_group %0;\n" :: "n"(N));
}
__device__ __forceinline__ void ldmx4(uint32_t* r, uint32_t a) {
    asm volatile("ldmatrix.sync.aligned.m8n8.x4.shared.b16 {%0,%1,%2,%3}, [%4];"
        : "=r"(r[0]), "=r"(r[1]), "=r"(r[2]), "=r"(r[3]) : "r"(a));
}
__device__ __forceinline__ void ldmx4t(uint32_t* r, uint32_t a) {
    asm volatile("ldmatrix.sync.aligned.m8n8.x4.trans.shared.b16 {%0,%1,%2,%3}, [%4];"
        : "=r"(r[0]), "=r"(r[1]), "=r"(r[2]), "=r"(r[3]) : "r"(a));
}
__device__ __forceinline__ void mma_f16(float* d, const uint32_t* a, const uint32_t* b) {
    asm volatile(
        "mma.sync.aligned.m16n8k16.row.col.f32.f16.f16.f32 "
        "{%0,%1,%2,%3}, {%4,%5,%6,%7}, {%8,%9}, {%0,%1,%2,%3};"
        : "+f"(d[0]), "+f"(d[1]), "+f"(d[2]), "+f"(d[3])
        : "r"(a[0]), "r"(a[1]), "r"(a[2]), "r"(a[3]), "r"(b[0]), "r"(b[1]));
}

// ---------------- weight fp32 -> fp16 ----------------
__global__ void cvt_w_kernel(const float* __restrict__ w0, const float* __restrict__ w1,
                             const float* __restrict__ w2, const float* __restrict__ w3,
                             __half* __restrict__ dst) {
    const int n = CH * CH;
    const float* srcs[4] = {w0, w1, w2, w3};
    for (int idx = blockIdx.x * blockDim.x + threadIdx.x; idx < 4 * n;
         idx += gridDim.x * blockDim.x)
        dst[idx] = __float2half(srcs[idx / n][idx % n]);
}

// ---------------- GroupNorm (fp32 in, fp16 out) ----------------
__global__ void gn_kernel(const float* __restrict__ x,
                          const float* __restrict__ gamma,
                          const float* __restrict__ beta,
                          __half* __restrict__ h) {
    const int b = blockIdx.x / NGROUPS;
    const int g = blockIdx.x % NGROUPS;
    const int n = CPG * HWN;
    const float* xp = x + ((size_t)b * CH + (size_t)g * CPG) * HWN;
    __half*      hp = h + ((size_t)b * CH + (size_t)g * CPG) * HWN;

    float s = 0.f, ss = 0.f;
    for (int i = threadIdx.x; i < n; i += 256) {
        float v = xp[i];
        s += v; ss += v * v;
    }
    __shared__ float sh1[256], sh2[256];
    sh1[threadIdx.x] = s; sh2[threadIdx.x] = ss;
    __syncthreads();
    for (int o = 128; o > 0; o >>= 1) {
        if (threadIdx.x < o) {
            sh1[threadIdx.x] += sh1[threadIdx.x + o];
            sh2[threadIdx.x] += sh2[threadIdx.x + o];
        }
        __syncthreads();
    }
    const float mean = sh1[0] / (float)n;
    const float var  = sh2[0] / (float)n - mean * mean;
    const float inv  = rsqrtf(var + 1e-6f);

    for (int i = threadIdx.x; i < n; i += 256) {
        int c = g * CPG + i / HWN;
        hp[i] = __float2half((xp[i] - mean) * inv * gamma[c] + beta[c]);
    }
}

// ---------------- FP16 tensor-core GEMM, 3-stage cp.async + ldmatrix -------
// C[m,n] = op(A)*op(B); ATRANS: A stored [K,M]; BTRANS: B stored [N,K]
// EPI: 1 +bias (half out), 2 +bias+res (float out),
//      4 exp(scale*acc)+rowsum (half out), 5 col-normalize by Lsum (half out)
template<bool ATRANS, bool BTRANS, int EPI>
__global__ __launch_bounds__(256)
void gemm_f16(const __half* __restrict__ Ag, const __half* __restrict__ Bg,
              void* __restrict__ Cg,
              const float* __restrict__ bias, const float* __restrict__ res,
              float* __restrict__ Lsum,
              int K, int lda, int ldb, int ldc,
              size_t strA, size_t strB, size_t strC, float scale)
{
    extern __shared__ __half smem[];
    constexpr int SA = ATRANS ? (TM + 8) : (TK + 8);   // halves
    constexpr int SB = BTRANS ? (TK + 8) : (TN + 8);
    constexpr int SZA = ATRANS ? TK * SA : TM * SA;
    constexpr int SZB = BTRANS ? TN * SB : TK * SB;
    constexpr int STG = SZA + SZB;

    const int bz = blockIdx.z;
    const int m0 = blockIdx.y * TM;
    const int n0 = blockIdx.x * TN;
    const __half* A = Ag + (size_t)bz * strA;
    const __half* B = Bg + (size_t)bz * strB;
    const float* R = (EPI == 2) ? (res + (size_t)bz * strC) : nullptr;
    float* L = (EPI == 4 || EPI == 5) ? (Lsum + (size_t)bz * HWN) : nullptr;

    const int tid  = threadIdx.x;
    const int wid  = tid >> 5;
    const int lane = tid & 31;
    const int gid  = lane >> 2;
    const int tig  = lane & 3;
    const int wm   = (wid >> 2) * 64;
    const int wn   = (wid & 3) * 32;
    const int lq   = lane >> 3;    // ldmatrix quadrant
    const int lr   = lane & 7;     // ldmatrix row

    auto copy_tile = [&](int kt, int st) {
        __half* as = smem + st * STG;
        __half* bs = as + SZA;
        const int k0 = kt * TK;
        #pragma unroll
        for (int i = 0; i < 2; i++) {
            int idx = tid + i * 256;
            if (ATRANS) {            // A[K,M], m contiguous: 32 rows x 16 chunks
                int k = idx >> 4, c = idx & 15;
                cp16(smem_u32(as + k * SA + c * 8), A + (size_t)(k0 + k) * lda + m0 + c * 8);
            } else {                 // A[M,K]: 128 rows x 4 chunks
                int m = idx >> 2, c = idx & 3;
                cp16(smem_u32(as + m * SA + c * 8), A + (size_t)(m0 + m) * lda + k0 + c * 8);
            }
        }
        #pragma unroll
        for (int i = 0; i < 2; i++) {
            int idx = tid + i * 256;
            if (BTRANS) {            // B[N,K]: 128 rows x 4 chunks
                int n = idx >> 2, c = idx & 3;
                cp16(smem_u32(bs + n * SB + c * 8), B + (size_t)(n0 + n) * ldb + k0 + c * 8);
            } else {                 // B[K,N]: 32 rows x 16 chunks
                int k = idx >> 4, c = idx & 15;
                cp16(smem_u32(bs + k * SB + c * 8), B + (size_t)(k0 + k) * ldb + n0 + c * 8);
            }
        }
    };

    float acc[4][4][4] = {};
    const int KT = K / TK;

    copy_tile(0, 0); cp_commit();
    copy_tile(1, 1); cp_commit();

    for (int kt = 0; kt < KT; kt++) {
        cp_wait<1>();
        __syncthreads();
        if (kt + 2 < KT) copy_tile(kt + 2, (kt + 2) % STAGES);
        cp_commit();

        const __half* as = smem + (kt % STAGES) * STG;
        const __half* bs = as + SZA;

        #pragma unroll
        for (int ks = 0; ks < 2; ks++) {
            const int kk = ks * 16;
            uint32_t a[4][4], b[2][4];
            #pragma unroll
            for (int i = 0; i < 4; i++) {
                const int mb = wm + i * 16;
                if (ATRANS) {
                    // stored [k][m]; rows = k; trans-ldmatrix
                    uint32_t addr = smem_u32(as + (size_t)(kk + (lq >> 1) * 8 + lr) * SA
                                                + mb + (lq & 1) * 8);
                    ldmx4t(a[i], addr);
                } else {
                    // stored [m][k]; rows = m
                    uint32_t addr = smem_u32(as + (size_t)(mb + lr + (lq & 1) * 8) * SA
                                                + kk + (lq >> 1) * 8);
                    ldmx4(a[i], addr);
                }
            }
            #pragma unroll
            for (int jj = 0; jj < 2; jj++) {
                const int nb = wn + jj * 16;
                if (BTRANS) {
                    // stored [n][k]; rows = n
                    uint32_t addr = smem_u32(bs + (size_t)(nb + (lq >> 1) * 8 + lr) * SB
                                                + kk + (lq & 1) * 8);
                    ldmx4(b[jj], addr);
                } else {
                    // stored [k][n]; rows = k; trans-ldmatrix
                    uint32_t addr = smem_u32(bs + (size_t)(kk + (lq & 1) * 8 + lr) * SB
                                                + nb + (lq >> 1) * 8);
                    ldmx4t(b[jj], addr);
                }
            }
            #pragma unroll
            for (int i = 0; i < 4; i++)
                #pragma unroll
                for (int j = 0; j < 4; j++)
                    mma_f16(acc[i][j], a[i], &b[j >> 1][(j & 1) * 2]);
        }
    }

    __syncthreads();

    // ---- epilogue ----
    #pragma unroll
    for (int i = 0; i < 4; i++) {
        const int r0 = m0 + wm + i * 16 + gid;
        float b0v = 0.f, b1v = 0.f;
        if (EPI == 1 || EPI == 2) { b0v = bias[r0]; b1v = bias[r0 + 8]; }
        float rsum0 = 0.f, rsum1 = 0.f;
        #pragma unroll
        for (int j = 0; j < 4; j++) {
            const int c0 = n0 + wn + j * 8 + tig * 2;
            size_t i0 = (size_t)r0 * ldc + c0;
            size_t i1 = (size_t)(r0 + 8) * ldc + c0;
            float2 v0 = make_float2(acc[i][j][0], acc[i][j][1]);
            float2 v1 = make_float2(acc[i][j][2], acc[i][j][3]);
            if (EPI == 1 || EPI == 2) { v0.x += b0v; v0.y += b0v; v1.x += b1v; v1.y += b1v; }
            if (EPI == 2) {
                float2 r0v = *reinterpret_cast<const float2*>(&R[i0]);
                float2 r1v = *reinterpret_cast<const float2*>(&R[i1]);
                v0.x += r0v.x; v0.y += r0v.y; v1.x += r1v.x; v1.y += r1v.y;
            }
            if (EPI == 4) {
                v0.x = __expf(v0.x * scale); v0.y = __expf(v0.y * scale);
                v1.x = __expf(v1.x * scale); v1.y = __expf(v1.y * scale);
                rsum0 += v0.x + v0.y;
                rsum1 += v1.x + v1.y;
            }
            if (EPI == 5) {
                float l0 = L[c0], l1 = L[c0 + 1];
                v0.x /= l0; v0.y /= l1;
                v1.x /= l0; v1.y /= l1;
            }
            if (EPI == 2) {
                float* C = (float*)Cg + (size_t)bz * strC;
                *reinterpret_cast<float2*>(&C[i0]) = v0;
                *reinterpret_cast<float2*>(&C[i1]) = v1;
            } else {
                __half* C = (__half*)Cg + (size_t)bz * strC;
                *reinterpret_cast<__half2*>(&C[i0]) = __floats2half2_rn(v0.x, v0.y);
                *reinterpret_cast<__half2*>(&C[i1]) = __floats2half2_rn(v1.x, v1.y);
            }
        }
        if (EPI == 4) {
            rsum0 += __shfl_xor_sync(0xffffffffu, rsum0, 1);
            rsum0 += __shfl_xor_sync(0xffffffffu, rsum0, 2);
            rsum1 += __shfl_xor_sync(0xffffffffu, rsum1, 1);
            rsum1 += __shfl_xor_sync(0xffffffffu, rsum1, 2);
            if (tig == 0) {
                atomicAdd(&L[r0], rsum0);
                atomicAdd(&L[r0 + 8], rsum1);
            }
        }
    }
}

// ---------------- launch ----------------
extern "C" void kernel_launch(void* const* d_in, const int* in_sizes, int n_in,
                              void* d_out, int out_size) {
    const float* x        = (const float*)d_in[0];
    const float* gn_gamma = (const float*)d_in[1];
    const float* gn_beta  = (const float*)d_in[2];
    const float* wq       = (const float*)d_in[3];
    const float* bq       = (const float*)d_in[4];
    const float* wk       = (const float*)d_in[5];
    const float* bk       = (const float*)d_in[6];
    const float* wv       = (const float*)d_in[7];
    const float* bv       = (const float*)d_in[8];
    const float* wo       = (const float*)d_in[9];
    const float* bo       = (const float*)d_in[10];
    float* out = (float*)d_out;

    __half *ph, *pq, *pk, *pv, *po, *ps, *pw;
    float *pl;
    cudaGetSymbolAddress((void**)&ph, g_h);
    cudaGetSymbolAddress((void**)&pq, g_q);
    cudaGetSymbolAddress((void**)&pk, g_k);
    cudaGetSymbolAddress((void**)&pv, g_v);
    cudaGetSymbolAddress((void**)&po, g_o);
    cudaGetSymbolAddress((void**)&ps, g_s);
    cudaGetSymbolAddress((void**)&pl, g_l);
    cudaGetSymbolAddress((void**)&pw, g_w);

    const size_t sCH = (size_t)CH * HWN;
    const size_t sSS = (size_t)HWN * HWN;
    const float scale = 0.04419417382415922f; // 512^-0.5
    const int WS = CH * CH;

    const int smem_ff = STAGES * (TM * (TK + 8) + TK * (TN + 8)) * 2;
    const int smem_tf = STAGES * (TK * (TM + 8) + TK * (TN + 8)) * 2;
    const int smem_ft = STAGES * (TM * (TK + 8) + TN * (TK + 8)) * 2;

    cudaFuncSetAttribute(gemm_f16<false, false, 1>, cudaFuncAttributeMaxDynamicSharedMemorySize, smem_ff);
    cudaFuncSetAttribute(gemm_f16<false, false, 2>, cudaFuncAttributeMaxDynamicSharedMemorySize, smem_ff);
    cudaFuncSetAttribute(gemm_f16<true,  false, 4>, cudaFuncAttributeMaxDynamicSharedMemorySize, smem_tf);
    cudaFuncSetAttribute(gemm_f16<false, true,  5>, cudaFuncAttributeMaxDynamicSharedMemorySize, smem_ft);

    // 0) weights -> fp16; zero row sums
    cvt_w_kernel<<<256, 256>>>(wq, wk, wv, wo, pw);
    cudaMemsetAsync(pl, 0, (size_t)BATCH * HWN * sizeof(float));

    // 1) GroupNorm -> fp16 h
    gn_kernel<<<BATCH * NGROUPS, 256>>>(x, gn_gamma, gn_beta, ph);

    // 2) q,k,v projections (fp16 out)
    dim3 pg(HWN / TN, CH / TM, BATCH);
    gemm_f16<false, false, 1><<<pg, 256, smem_ff>>>(pw + 0 * WS, ph, pq, bq, nullptr, nullptr,
        CH, CH, HWN, HWN, 0, sCH, sCH, 1.f);
    gemm_f16<false, false, 1><<<pg, 256, smem_ff>>>(pw + 1 * WS, ph, pk, bk, nullptr, nullptr,
        CH, CH, HWN, HWN, 0, sCH, sCH, 1.f);
    gemm_f16<false, false, 1><<<pg, 256, smem_ff>>>(pw + 2 * WS, ph, pv, bv, nullptr, nullptr,
        CH, CH, HWN, HWN, 0, sCH, sCH, 1.f);

    // 3) P~[n,m] = exp(scale * Q^T K) (fp16), row sums -> g_l
    dim3 sg(HWN / TN, HWN / TM, BATCH);
    gemm_f16<true, false, 4><<<sg, 256, smem_tf>>>(pq, pk, ps, nullptr, nullptr, pl,
        CH, HWN, HWN, HWN, sCH, sCH, sSS, scale);

    // 4) O[c,n] = (sum_m V[c,m] P~[n,m]) / l[n] (fp16)
    dim3 ag(HWN / TN, CH / TM, BATCH);
    gemm_f16<false, true, 5><<<ag, 256, smem_ft>>>(pv, ps, po, nullptr, nullptr, pl,
        HWN, HWN, HWN, HWN, sCH, sSS, sCH, 1.f);

    // 5) out projection + bias + residual (fp32 out)
    gemm_f16<false, false, 2><<<pg, 256, smem_ff>>>(pw + 3 * WS, po, out, bo, x, nullptr,
        CH, CH, HWN, HWN, 0, sCH, sCH, 1.f);
}